// round 4
// baseline (speedup 1.0000x reference)
#include <cuda_runtime.h>
#include <math.h>
#include <stdint.h>
#include <stddef.h>

#define N_TOK 2048
#define HIDD  1024
#define NH    16
#define SMS   68

// ---------------- device scratch (no allocation allowed) ----------------
__device__ float g_q[N_TOK * HIDD];
__device__ float g_k[N_TOK * HIDD];
__device__ float g_v[N_TOK * HIDD];
__device__ float g_attn[N_TOK * HIDD];
__device__ float g_feat[48 * N_TOK];   // rows 0-15: 2*r*bp ; 16-31: u ; 32-47: pe/(2*sqrt2)
__device__ float g_scal[3 * N_TOK];    // r, 2*nb*r, ne/16
__device__ float g_cos[N_TOK * 32];
__device__ float g_sin[N_TOK * 32];

// ---------------- per-node manifold features + rope tables ----------------
__global__ void feat_kernel(const float* __restrict__ pos) {
    int n = blockIdx.x * blockDim.x + threadIdx.x;
    if (n >= N_TOK) return;
    const float* p = pos + n * 48;
    float ph[16], ps[16], pe[16];
    float s2 = 0.f, su = 0.f, se = 0.f;
#pragma unroll
    for (int i = 0; i < 16; i++) { ph[i] = p[i];      s2 += ph[i]*ph[i]; }
#pragma unroll
    for (int i = 0; i < 16; i++) { ps[i] = p[16+i];   su += ps[i]*ps[i]; }
#pragma unroll
    for (int i = 0; i < 16; i++) { pe[i] = p[32+i];   se += pe[i]*pe[i]; }
    float bn = sqrtf(s2);
    float sc = 0.9f / (1.f + bn);          // bp = sc * ph
    float nb = sc * sc * s2;               // |bp|^2
    float r  = 1.f / (1.f - nb);
    float un = rsqrtf(su);
#pragma unroll
    for (int i = 0; i < 16; i++) g_feat[i*N_TOK + n]      = 2.f * r * sc * ph[i];
#pragma unroll
    for (int i = 0; i < 16; i++) g_feat[(16+i)*N_TOK + n] = ps[i] * un;
#pragma unroll
    for (int i = 0; i < 16; i++) g_feat[(32+i)*N_TOK + n] = pe[i] * 0.35355339059327373f;
    g_scal[n]           = r;
    g_scal[N_TOK + n]   = 2.f * nb * r;
    g_scal[2*N_TOK + n] = se * 0.0625f;
#pragma unroll
    for (int j = 0; j < 32; j++) {
        float invf = __expf(-(float)j * (9.2103403719761836f / 32.f)); // 10000^(-j/32)
        float ang = p[j] * invf;
        g_cos[n*32 + j] = cosf(ang);
        g_sin[n*32 + j] = sinf(ang);
    }
}

// ---------------- in-place mRoPE on g_q / g_k ----------------
__global__ void rope_kernel() {
    int g = blockIdx.x * blockDim.x + threadIdx.x;
    if (g >= N_TOK * 512) return;
    int n = g >> 9; int t = g & 511; int hh = t >> 5; int j = t & 31;
    float c = g_cos[n*32 + j], s = g_sin[n*32 + j];
    int b = n * HIDD + hh * 64 + j;
    float a1 = g_q[b], a2 = g_q[b + 32];
    g_q[b] = a1*c - a2*s; g_q[b + 32] = a1*s + a2*c;
    float b1 = g_k[b], b2 = g_k[b + 32];
    g_k[b] = b1*c - b2*s; g_k[b + 32] = b1*s + b2*c;
}

// ---------------- fp32 SGEMM 128x128 tile, z selects (B,C) triple ----------------
__global__ __launch_bounds__(256, 2) void sgemm_kernel(
    const float* __restrict__ A,
    const float* __restrict__ B0, const float* __restrict__ B1, const float* __restrict__ B2,
    float* __restrict__ C0, float* __restrict__ C1, float* __restrict__ C2,
    const float* __restrict__ bias, int M, int Nc, int K)
{
    const float* B = (blockIdx.z == 0) ? B0 : ((blockIdx.z == 1) ? B1 : B2);
    float*       C = (blockIdx.z == 0) ? C0 : ((blockIdx.z == 1) ? C1 : C2);
    __shared__ float As[16][132];
    __shared__ float Bs[16][132];
    const int tid = threadIdx.x;
    const int row0 = blockIdx.y * 128, col0 = blockIdx.x * 128;
    const int tr = tid >> 4, tc = tid & 15;
    const int arow = tid >> 2, acol = (tid & 3) << 2;
    const int brow = tid >> 5, bcol = (tid & 31) << 2;
    float acc[8][8] = {};
    for (int k0 = 0; k0 < K; k0 += 16) {
#pragma unroll
        for (int i = 0; i < 2; i++) {
            float4 a = *(const float4*)(A + (size_t)(row0 + arow + i*64)*K + k0 + acol);
            As[acol+0][arow + i*64] = a.x;
            As[acol+1][arow + i*64] = a.y;
            As[acol+2][arow + i*64] = a.z;
            As[acol+3][arow + i*64] = a.w;
        }
#pragma unroll
        for (int i = 0; i < 2; i++)
            *(float4*)&Bs[brow + i*8][bcol] =
                *(const float4*)(B + (size_t)(k0 + brow + i*8)*Nc + col0 + bcol);
        __syncthreads();
#pragma unroll
        for (int kk = 0; kk < 16; kk++) {
            float ar[8], br[8];
            *(float4*)&ar[0] = *(float4*)&As[kk][tr*8];
            *(float4*)&ar[4] = *(float4*)&As[kk][tr*8 + 4];
            *(float4*)&br[0] = *(float4*)&Bs[kk][tc*8];
            *(float4*)&br[4] = *(float4*)&Bs[kk][tc*8 + 4];
#pragma unroll
            for (int i = 0; i < 8; i++)
#pragma unroll
                for (int j = 0; j < 8; j++)
                    acc[i][j] = fmaf(ar[i], br[j], acc[i][j]);
        }
        __syncthreads();
    }
#pragma unroll
    for (int i = 0; i < 8; i++) {
        int row = row0 + tr*8 + i;
#pragma unroll
        for (int j4 = 0; j4 < 2; j4++) {
            int col = col0 + tc*8 + j4*4;
            float4 o;
            o.x = acc[i][j4*4+0]; o.y = acc[i][j4*4+1];
            o.z = acc[i][j4*4+2]; o.w = acc[i][j4*4+3];
            if (bias) {
                float4 bv = *(const float4*)(bias + col);
                o.x += bv.x; o.y += bv.y; o.z += bv.z; o.w += bv.w;
            }
            *(float4*)(C + (size_t)row*Nc + col) = o;
        }
    }
}

// ---------------- fused flash attention with manifold kernel bias ----------------
// grid (32 q-tiles, 16 heads), 256 threads, dynamic smem
__global__ __launch_bounds__(256) void attn_kernel(
    const int* __restrict__ mask,
    const float* __restrict__ kw,
    const float* __restrict__ beta)
{
    extern __shared__ float smx[];
    float* qT   = smx;                 // [64 d][SMS] dim-major
    float* kT   = qT  + 64*SMS;        // [64 d][SMS]
    float* vS   = kT  + 64*SMS;        // [64 key][SMS] key-major
    float* Ss   = vS  + 64*SMS;        // P tile [64 q][SMS]
    float* fqT  = Ss  + 64*SMS;        // [48][SMS]
    float* fkT  = fqT + 48*SMS;        // [48][SMS]
    float* s_sq = fkT + 48*SMS;        // [3][64]
    float* s_sk = s_sq + 192;          // [3][64]
    float* s_mi = s_sk + 192;          // [64]
    float* s_li = s_mi + 64;           // [64]
    float* s_al = s_li + 64;           // [64]
    float* red  = s_al + 64;           // [64*16]
    unsigned char* s_msk = (unsigned char*)(red + 1024); // [64*64]

    const int tid = threadIdx.x;
    const int h   = blockIdx.y;
    const int q0g = blockIdx.x << 6;

    float w0 = kw[h*3+0], w1 = kw[h*3+1], w2 = kw[h*3+2];
    float wm = fmaxf(w0, fmaxf(w1, w2));
    float e0 = __expf(w0 - wm), e1 = __expf(w1 - wm), e2 = __expf(w2 - wm);
    float bscl = beta[h] / (e0 + e1 + e2);
    const float bw0 = e0*bscl, bw1 = e1*bscl, bw2 = e2*bscl;

    for (int idx = tid; idx < 1024; idx += 256) {
        int i = idx >> 4, c = (idx & 15) << 2;
        float4 qv = *(const float4*)(g_q + (size_t)(q0g + i)*HIDD + h*64 + c);
        qT[(c+0)*SMS + i] = qv.x; qT[(c+1)*SMS + i] = qv.y;
        qT[(c+2)*SMS + i] = qv.z; qT[(c+3)*SMS + i] = qv.w;
    }
    for (int idx = tid; idx < 768; idx += 256) {
        int p = idx >> 4, c = (idx & 15) << 2;
        *(float4*)(fqT + p*SMS + c) = *(const float4*)(g_feat + p*N_TOK + q0g + c);
    }
    if (tid < 192) s_sq[tid] = g_scal[(tid >> 6)*N_TOK + q0g + (tid & 63)];
    if (tid < 64) { s_mi[tid] = -1e30f; s_li[tid] = 0.f; }

    const int ty = tid >> 4, tx = tid & 15;
    const int q0 = ty << 2, k0 = tx << 2;
    float O[4][4] = {};

    for (int kt = 0; kt < 32; kt++) {
        const int k0g = kt << 6;
        __syncthreads();  // previous tile's consumers done

        for (int idx = tid; idx < 1024; idx += 256) {
            int m = idx >> 4, c = (idx & 15) << 2;
            size_t gb = (size_t)(k0g + m)*HIDD + h*64 + c;
            float4 kv = *(const float4*)(g_k + gb);
            kT[(c+0)*SMS + m] = kv.x; kT[(c+1)*SMS + m] = kv.y;
            kT[(c+2)*SMS + m] = kv.z; kT[(c+3)*SMS + m] = kv.w;
            *(float4*)(vS + m*SMS + c) = *(const float4*)(g_v + gb);
        }
        for (int idx = tid; idx < 768; idx += 256) {
            int p = idx >> 4, c = (idx & 15) << 2;
            *(float4*)(fkT + p*SMS + c) = *(const float4*)(g_feat + p*N_TOK + k0g + c);
        }
        if (tid < 192) s_sk[tid] = g_scal[(tid >> 6)*N_TOK + k0g + (tid & 63)];
        // mask is int32 (bool marshalled as int32 by the harness)
        for (int idx = tid; idx < 4096; idx += 256) {
            int i = idx >> 6, j = idx & 63;
            s_msk[idx] =
                (unsigned char)(mask[(size_t)(q0g + i)*N_TOK + k0g + j] != 0);
        }
        __syncthreads();

        float S[4][4] = {}, bb_[4][4], t[4][4];
        // QK dot (64 dims)
#pragma unroll
        for (int d = 0; d < 64; d++) {
            float4 a4 = *(float4*)(qT + d*SMS + q0);
            float4 b4 = *(float4*)(kT + d*SMS + k0);
            float aa[4] = {a4.x,a4.y,a4.z,a4.w}, bv[4] = {b4.x,b4.y,b4.z,b4.w};
#pragma unroll
            for (int i = 0; i < 4; i++)
#pragma unroll
                for (int j = 0; j < 4; j++) S[i][j] = fmaf(aa[i], bv[j], S[i][j]);
        }
        // k_h
#pragma unroll
        for (int i = 0; i < 4; i++)
#pragma unroll
            for (int j = 0; j < 4; j++) t[i][j] = 0.f;
#pragma unroll
        for (int p = 0; p < 16; p++) {
            float4 a4 = *(float4*)(fqT + p*SMS + q0);
            float4 b4 = *(float4*)(fkT + p*SMS + k0);
            float aa[4] = {a4.x,a4.y,a4.z,a4.w}, bv[4] = {b4.x,b4.y,b4.z,b4.w};
#pragma unroll
            for (int i = 0; i < 4; i++)
#pragma unroll
                for (int j = 0; j < 4; j++) t[i][j] = fmaf(aa[i], bv[j], t[i][j]);
        }
        {
            float rq[4], cq[4], rk[4], ck[4];
#pragma unroll
            for (int i = 0; i < 4; i++) { rq[i] = s_sq[q0+i]; cq[i] = s_sq[64+q0+i]; }
#pragma unroll
            for (int j = 0; j < 4; j++) { rk[j] = s_sk[k0+j]; ck[j] = s_sk[64+k0+j]; }
#pragma unroll
            for (int i = 0; i < 4; i++)
#pragma unroll
                for (int j = 0; j < 4; j++) {
                    float delta = fmaxf(fmaf(cq[i], rk[j], ck[j]*rq[i]) - t[i][j], 0.f);
                    bb_[i][j] = bw0 * __expf(-delta);
                }
        }
        // k_s
#pragma unroll
        for (int i = 0; i < 4; i++)
#pragma unroll
            for (int j = 0; j < 4; j++) t[i][j] = 0.f;
#pragma unroll
        for (int p = 0; p < 16; p++) {
            float4 a4 = *(float4*)(fqT + (16+p)*SMS + q0);
            float4 b4 = *(float4*)(fkT + (16+p)*SMS + k0);
            float aa[4] = {a4.x,a4.y,a4.z,a4.w}, bv[4] = {b4.x,b4.y,b4.z,b4.w};
#pragma unroll
            for (int i = 0; i < 4; i++)
#pragma unroll
                for (int j = 0; j < 4; j++) t[i][j] = fmaf(aa[i], bv[j], t[i][j]);
        }
#pragma unroll
        for (int i = 0; i < 4; i++)
#pragma unroll
            for (int j = 0; j < 4; j++) {
                float cs = fminf(fmaxf(t[i][j], -1.f), 1.f);
                bb_[i][j] = fmaf(bw1, __expf(cs - 1.f), bb_[i][j]);
            }
        // k_e
#pragma unroll
        for (int i = 0; i < 4; i++)
#pragma unroll
            for (int j = 0; j < 4; j++) t[i][j] = 0.f;
#pragma unroll
        for (int p = 0; p < 16; p++) {
            float4 a4 = *(float4*)(fqT + (32+p)*SMS + q0);
            float4 b4 = *(float4*)(fkT + (32+p)*SMS + k0);
            float aa[4] = {a4.x,a4.y,a4.z,a4.w}, bv[4] = {b4.x,b4.y,b4.z,b4.w};
#pragma unroll
            for (int i = 0; i < 4; i++)
#pragma unroll
                for (int j = 0; j < 4; j++) t[i][j] = fmaf(aa[i], bv[j], t[i][j]);
        }
        {
            float nq[4], nk[4];
#pragma unroll
            for (int i = 0; i < 4; i++) nq[i] = s_sq[128+q0+i];
#pragma unroll
            for (int j = 0; j < 4; j++) nk[j] = s_sk[128+k0+j];
#pragma unroll
            for (int i = 0; i < 4; i++)
#pragma unroll
                for (int j = 0; j < 4; j++) {
                    float sq = fmaxf(nq[i] + nk[j] - t[i][j], 0.f);
                    bb_[i][j] = fmaf(bw2, __expf(-sq), bb_[i][j]);
                }
        }
        // combine + mask, local row max
        float lmax[4] = {-1e30f, -1e30f, -1e30f, -1e30f};
#pragma unroll
        for (int i = 0; i < 4; i++)
#pragma unroll
            for (int j = 0; j < 4; j++) {
                float v = S[i][j]*0.125f + bb_[i][j];
                if (!s_msk[(q0+i)*64 + k0 + j]) v = -1e30f;
                S[i][j] = v;
                lmax[i] = fmaxf(lmax[i], v);
            }
#pragma unroll
        for (int i = 0; i < 4; i++) red[(q0+i)*16 + tx] = lmax[i];
        __syncthreads();
        if (tid < 64) {
            float m = -1e30f;
#pragma unroll
            for (int t2 = 0; t2 < 16; t2++) m = fmaxf(m, red[tid*16 + t2]);
            float mo = s_mi[tid], mn = fmaxf(mo, m);
            s_mi[tid] = mn;
            float a = __expf(mo - mn);
            s_al[tid] = a;
            s_li[tid] *= a;
        }
        __syncthreads();
        float lsum[4] = {};
#pragma unroll
        for (int i = 0; i < 4; i++) {
            float mn = s_mi[q0+i];
#pragma unroll
            for (int j = 0; j < 4; j++) {
                float p = __expf(S[i][j] - mn);
                Ss[(q0+i)*SMS + k0 + j] = p;
                lsum[i] += p;
            }
        }
#pragma unroll
        for (int i = 0; i < 4; i++) red[(q0+i)*16 + tx] = lsum[i];
        __syncthreads();
        if (tid < 64) {
            float s = 0.f;
#pragma unroll
            for (int t2 = 0; t2 < 16; t2++) s += red[tid*16 + t2];
            s_li[tid] += s;
        }
        __syncthreads();
        // O = O*alpha + P @ V  (cols d0 = tx*4)
        const int d0 = tx << 2;
#pragma unroll
        for (int i = 0; i < 4; i++) {
            float a = s_al[q0+i];
#pragma unroll
            for (int j = 0; j < 4; j++) O[i][j] *= a;
        }
        for (int m = 0; m < 64; m++) {
            float4 v4 = *(float4*)(vS + m*SMS + d0);
            float vv[4] = {v4.x, v4.y, v4.z, v4.w};
#pragma unroll
            for (int i = 0; i < 4; i++) {
                float p = Ss[(q0+i)*SMS + m];
#pragma unroll
                for (int j = 0; j < 4; j++) O[i][j] = fmaf(p, vv[j], O[i][j]);
            }
        }
    }
    // write normalized output
    const int d0 = tx << 2;
#pragma unroll
    for (int i = 0; i < 4; i++) {
        float inv = 1.f / s_li[q0+i];
        float4 o;
        o.x = O[i][0]*inv; o.y = O[i][1]*inv; o.z = O[i][2]*inv; o.w = O[i][3]*inv;
        *(float4*)(g_attn + (size_t)(q0g + q0 + i)*HIDD + h*64 + d0) = o;
    }
}

extern "C" void kernel_launch(void* const* d_in, const int* in_sizes, int n_in,
                              void* d_out, int out_size) {
    const float* h    = (const float*)d_in[0];
    const float* pos  = (const float*)d_in[1];
    const int*   mask = (const int*)d_in[2];
    const float* Wq   = (const float*)d_in[3];
    const float* Wk   = (const float*)d_in[4];
    const float* Wv   = (const float*)d_in[5];
    const float* Wo   = (const float*)d_in[6];
    const float* bo   = (const float*)d_in[7];
    const float* kw   = (const float*)d_in[8];
    const float* beta = (const float*)d_in[9];
    float* out = (float*)d_out;

    float *q, *k, *v, *attn;
    cudaGetSymbolAddress((void**)&q,    g_q);
    cudaGetSymbolAddress((void**)&k,    g_k);
    cudaGetSymbolAddress((void**)&v,    g_v);
    cudaGetSymbolAddress((void**)&attn, g_attn);

    feat_kernel<<<8, 256>>>(pos);
    sgemm_kernel<<<dim3(8, 16, 3), 256>>>(h, Wq, Wk, Wv, q, k, v, nullptr,
                                          N_TOK, HIDD, HIDD);
    rope_kernel<<<4096, 256>>>();

    const int SMEM = 25536 * 4 + 4096;  // 106240 B
    cudaFuncSetAttribute(attn_kernel,
                         cudaFuncAttributeMaxDynamicSharedMemorySize, SMEM);
    attn_kernel<<<dim3(32, 16), 256, SMEM>>>(mask, kw, beta);

    sgemm_kernel<<<dim3(8, 16, 1), 256>>>(attn, Wo, Wo, Wo, out, out, out, bo,
                                          N_TOK, HIDD, HIDD);
}